// round 1
// baseline (speedup 1.0000x reference)
#include <cuda_runtime.h>
#include <math.h>

#define BATCH 32
#define SEQT  2048
#define DIM   512
#define ROWS  (BATCH*SEQT)   // 65536

// scratch (no allocs allowed)
__device__ float g_ait[ROWS];
__device__ float g_a[ROWS];

// ---------------- Kernel 1: fused GEMM + tanh + dot(u) -> g_ait -------------
#define BM 128
#define BN 64
#define BK 16
#define TM 8
#define TN 4

__global__ __launch_bounds__(256) void gemm_tanh_dot(
    const float* __restrict__ x, const float* __restrict__ W,
    const float* __restrict__ bias, const float* __restrict__ u)
{
    __shared__ float As[BK][BM];
    __shared__ float Bs[BK][BN];

    const int tid = threadIdx.x;
    const int tx  = tid & 15;   // N direction (16 groups of TN=4 cols)
    const int ty  = tid >> 4;   // M direction (16 groups of TM=8 rows)
    const int row0 = blockIdx.x * BM;
    const int col0 = blockIdx.y * BN;

    float acc[TM][TN];
    #pragma unroll
    for (int i = 0; i < TM; i++)
        #pragma unroll
        for (int j = 0; j < TN; j++) acc[i][j] = 0.f;

    for (int k0 = 0; k0 < DIM; k0 += BK) {
        // Load A tile (128x16) transposed into As: 512 float4, 2 per thread
        #pragma unroll
        for (int i = 0; i < 2; i++) {
            int idx = tid * 2 + i;
            int ar = idx >> 2;
            int ac = (idx & 3) * 4;
            float4 v = *(const float4*)(x + (size_t)(row0 + ar) * DIM + k0 + ac);
            As[ac + 0][ar] = v.x;
            As[ac + 1][ar] = v.y;
            As[ac + 2][ar] = v.z;
            As[ac + 3][ar] = v.w;
        }
        // Load B tile (16x64): 256 float4, 1 per thread
        {
            int br = tid >> 4;
            int bc = (tid & 15) * 4;
            float4 v = *(const float4*)(W + (size_t)(k0 + br) * DIM + col0 + bc);
            *(float4*)&Bs[br][bc] = v;
        }
        __syncthreads();

        #pragma unroll
        for (int k = 0; k < BK; k++) {
            float af[TM], bf[TN];
            #pragma unroll
            for (int i = 0; i < TM; i++) af[i] = As[k][ty * TM + i];
            #pragma unroll
            for (int j = 0; j < TN; j++) bf[j] = Bs[k][tx * TN + j];
            #pragma unroll
            for (int i = 0; i < TM; i++)
                #pragma unroll
                for (int j = 0; j < TN; j++)
                    acc[i][j] = fmaf(af[i], bf[j], acc[i][j]);
        }
        __syncthreads();
    }

    // Epilogue: tanh(z + b) * u, reduce over the 64 columns this block owns
    float bv[TN], uv[TN];
    #pragma unroll
    for (int j = 0; j < TN; j++) {
        int c = col0 + tx * TN + j;
        bv[j] = bias[c];
        uv[j] = u[c];
    }
    #pragma unroll
    for (int i = 0; i < TM; i++) {
        float p = 0.f;
        #pragma unroll
        for (int j = 0; j < TN; j++)
            p += tanhf(acc[i][j] + bv[j]) * uv[j];
        // reduce across the 16 tx lanes (within 16-lane segment of warp)
        #pragma unroll
        for (int off = 8; off > 0; off >>= 1)
            p += __shfl_xor_sync(0xffffffffu, p, off, 16);
        if (tx == 0)
            atomicAdd(&g_ait[row0 + ty * TM + i], p);
    }
}

// ---------------- Kernel 2: per-batch exp + normalize over T ----------------
__global__ __launch_bounds__(256) void softmax_norm()
{
    const int b = blockIdx.x;
    const int tid = threadIdx.x;
    __shared__ float red[256];

    float e[8];
    float s = 0.f;
    #pragma unroll
    for (int i = 0; i < 8; i++) {
        float v = g_ait[b * SEQT + i * 256 + tid];
        e[i] = expf(v);
        s += e[i];
    }
    red[tid] = s;
    __syncthreads();
    #pragma unroll
    for (int stride = 128; stride > 0; stride >>= 1) {
        if (tid < stride) red[tid] += red[tid + stride];
        __syncthreads();
    }
    float inv = 1.0f / (red[0] + 1e-7f);
    #pragma unroll
    for (int i = 0; i < 8; i++)
        g_a[b * SEQT + i * 256 + tid] = e[i] * inv;
}

// ---------------- Kernel 3: weighted pooling out[b,d] = sum_t x*a -----------
__global__ __launch_bounds__(256) void pool(
    const float* __restrict__ x, float* __restrict__ out)
{
    const int b  = blockIdx.x;
    const int tc = blockIdx.y;        // 16 chunks of 128 timesteps
    const int tid = threadIdx.x;
    __shared__ float sa[128];

    if (tid < 128)
        sa[tid] = g_a[b * SEQT + tc * 128 + tid];
    __syncthreads();

    const float* xp = x + (size_t)b * SEQT * DIM + (size_t)tc * 128 * DIM;
    float acc0 = 0.f, acc1 = 0.f;
    #pragma unroll 4
    for (int t = 0; t < 128; t++) {
        float av = sa[t];
        acc0 = fmaf(xp[(size_t)t * DIM + tid],       av, acc0);
        acc1 = fmaf(xp[(size_t)t * DIM + tid + 256], av, acc1);
    }
    atomicAdd(&out[b * DIM + tid],       acc0);
    atomicAdd(&out[b * DIM + tid + 256], acc1);
}

// ---------------------------------------------------------------------------
extern "C" void kernel_launch(void* const* d_in, const int* in_sizes, int n_in,
                              void* d_out, int out_size)
{
    const float* x    = (const float*)d_in[0];  // [32, 2048, 512]
    const float* W    = (const float*)d_in[1];  // [512, 512]
    const float* bias = (const float*)d_in[2];  // [512]
    const float* u    = (const float*)d_in[3];  // [512]
    float* out = (float*)d_out;                 // [32, 512]

    void* aitp = nullptr;
    cudaGetSymbolAddress(&aitp, g_ait);
    cudaMemsetAsync(aitp, 0, ROWS * sizeof(float));
    cudaMemsetAsync(d_out, 0, BATCH * DIM * sizeof(float));

    dim3 g1(ROWS / BM, DIM / BN);   // (512, 8)
    gemm_tanh_dot<<<g1, 256>>>(x, W, bias, u);
    softmax_norm<<<BATCH, 256>>>();
    pool<<<dim3(BATCH, 16), 256>>>(x, out);
}

// round 5
// speedup vs baseline: 4.8518x; 4.8518x over previous
#include <cuda_runtime.h>
#include <cuda_fp16.h>
#include <math.h>
#include <stdint.h>

#define BATCH 32
#define SEQT  2048
#define DIM   512
#define ROWS  (BATCH*SEQT)   // 65536

// scratch (no runtime allocs allowed)
__device__ float  g_ait[ROWS];
__device__ float  g_a[ROWS];
__device__ __half g_wh[DIM*DIM];      // W transposed: g_wh[n*DIM+k] = (half)W[k*DIM+n]
__device__ __half g_xh[(size_t)ROWS*DIM];   // x in fp16

// ---------------------------------------------------------------- helpers
__device__ __forceinline__ uint32_t smem_u32(const void* p){
    uint32_t a;
    asm("{ .reg .u64 t; cvta.to.shared.u64 t, %1; cvt.u32.u64 %0, t; }" : "=r"(a) : "l"(p));
    return a;
}
__device__ __forceinline__ void ldm4(uint32_t* r, uint32_t addr){
    asm volatile("ldmatrix.sync.aligned.m8n8.x4.shared.b16 {%0,%1,%2,%3}, [%4];"
                 : "=r"(r[0]),"=r"(r[1]),"=r"(r[2]),"=r"(r[3]) : "r"(addr));
}
__device__ __forceinline__ void mma16816(float* c, const uint32_t* a, const uint32_t* b){
    asm volatile("mma.sync.aligned.m16n8k16.row.col.f32.f16.f16.f32 "
                 "{%0,%1,%2,%3}, {%4,%5,%6,%7}, {%8,%9}, {%0,%1,%2,%3};"
                 : "+f"(c[0]),"+f"(c[1]),"+f"(c[2]),"+f"(c[3])
                 : "r"(a[0]),"r"(a[1]),"r"(a[2]),"r"(a[3]), "r"(b[0]),"r"(b[1]));
}
__device__ __forceinline__ void cpasync16(uint32_t dst, const void* src){
    asm volatile("cp.async.cg.shared.global [%0], [%1], 16;" :: "r"(dst), "l"(src) : "memory");
}
__device__ __forceinline__ float tanha(float x){
    float t; asm("tanh.approx.f32 %0, %1;" : "=f"(t) : "f"(x)); return t;
}

// ---------------- prep: convert inputs to fp16 ------------------------------
__global__ __launch_bounds__(256) void prep_x(const float* __restrict__ x){
    size_t i = ((size_t)blockIdx.x * 256 + threadIdx.x) * 8;
    float4 v0 = *(const float4*)(x + i);
    float4 v1 = *(const float4*)(x + i + 4);
    __half2 h0 = __floats2half2_rn(v0.x, v0.y);
    __half2 h1 = __floats2half2_rn(v0.z, v0.w);
    __half2 h2 = __floats2half2_rn(v1.x, v1.y);
    __half2 h3 = __floats2half2_rn(v1.z, v1.w);
    uint4 o;
    o.x = *(uint32_t*)&h0; o.y = *(uint32_t*)&h1;
    o.z = *(uint32_t*)&h2; o.w = *(uint32_t*)&h3;
    *(uint4*)(g_xh + i) = o;
}
__global__ __launch_bounds__(256) void prep_w(const float* __restrict__ W){
    int n = blockIdx.x;
    for (int k = threadIdx.x; k < DIM; k += 256)
        g_wh[(size_t)n*DIM + k] = __float2half_rn(W[(size_t)k*DIM + n]);
}

// ---------------- Kernel 1: fp16 tensor-core GEMM + fused epilogue ----------
#define BM 128
#define BN 128
#define BK 32
#define KROW 40                       // padded row pitch in halfs (80 bytes)
#define ABUF (BM*KROW)                // halfs per A buffer (10240B)
#define BBUF (BN*KROW)

__global__ __launch_bounds__(256, 2) void gemm_tc(
    const float* __restrict__ bias, const float* __restrict__ u)
{
    __shared__ __half sA[2][ABUF];
    __shared__ __half sB[2][BBUF];

    const int tid  = threadIdx.x;
    const int wid  = tid >> 5;
    const int lane = tid & 31;
    const int col0 = blockIdx.x * BN;   // N blocks (4)
    const int row0 = blockIdx.y * BM;   // M blocks (512)

    const int warp_m = (wid & 3) * 32;  // 4 warps along M
    const int warp_n = (wid >> 2) * 64; // 2 warps along N

    const uint32_t sA0 = smem_u32(&sA[0][0]);
    const uint32_t sB0 = smem_u32(&sB[0][0]);

    // cp.async per-thread chunk coords: chunk = 16B = 8 halfs
    const int chr0 = tid >> 2;          // row for chunk tid
    const int chc0 = (tid & 3) * 8;     // k-offset halfs
    const int chr1 = (tid + 256) >> 2;
    const int chc1 = ((tid + 256) & 3) * 8;

    const __half* Abase = g_xh + (size_t)row0 * DIM;
    const __half* Bbase = g_wh + (size_t)col0 * DIM;

    float acc[2][8][4];
    #pragma unroll
    for (int mt = 0; mt < 2; mt++)
        #pragma unroll
        for (int nt = 0; nt < 8; nt++)
            #pragma unroll
            for (int e = 0; e < 4; e++) acc[mt][nt][e] = 0.f;

    // precomputed ldmatrix per-thread offsets (bytes)
    const uint32_t aoff = (uint32_t)((warp_m + (lane & 15)) * 80 + (lane >> 4) * 16);
    const uint32_t boff = (uint32_t)((warp_n + (lane & 7) + (lane >> 4) * 8) * 80
                                     + ((lane >> 3) & 1) * 16);

#define STAGE(cidx, buf) do{                                                       \
    int k0h = (cidx) * BK;                                                         \
    uint32_t dA = sA0 + (buf) * (ABUF*2);                                          \
    uint32_t dB = sB0 + (buf) * (BBUF*2);                                          \
    cpasync16(dA + chr0*80 + chc0*2, Abase + (size_t)chr0*DIM + k0h + chc0);       \
    cpasync16(dA + chr1*80 + chc1*2, Abase + (size_t)chr1*DIM + k0h + chc1);       \
    cpasync16(dB + chr0*80 + chc0*2, Bbase + (size_t)chr0*DIM + k0h + chc0);       \
    cpasync16(dB + chr1*80 + chc1*2, Bbase + (size_t)chr1*DIM + k0h + chc1);       \
    asm volatile("cp.async.commit_group;" ::: "memory");                           \
}while(0)

    STAGE(0, 0);

    for (int c = 0; c < DIM/BK; c++){
        const int buf = c & 1;
        if (c + 1 < DIM/BK){
            STAGE(c + 1, buf ^ 1);
            asm volatile("cp.async.wait_group 1;" ::: "memory");
        } else {
            asm volatile("cp.async.wait_group 0;" ::: "memory");
        }
        __syncthreads();

        const uint32_t bA = sA0 + buf * (ABUF*2);
        const uint32_t bB = sB0 + buf * (BBUF*2);
        #pragma unroll
        for (int kk = 0; kk < BK; kk += 16){
            uint32_t af[2][4];
            #pragma unroll
            for (int mt = 0; mt < 2; mt++)
                ldm4(af[mt], bA + aoff + (uint32_t)(mt*16*80 + kk*2));
            uint32_t bf[8][2];
            #pragma unroll
            for (int q = 0; q < 4; q++){
                uint32_t r[4];
                ldm4(r, bB + boff + (uint32_t)(q*16*80 + kk*2));
                bf[2*q][0] = r[0]; bf[2*q][1] = r[1];
                bf[2*q+1][0] = r[2]; bf[2*q+1][1] = r[3];
            }
            #pragma unroll
            for (int mt = 0; mt < 2; mt++)
                #pragma unroll
                for (int nt = 0; nt < 8; nt++)
                    mma16816(acc[mt][nt], af[mt], bf[nt]);
        }
        __syncthreads();
    }

    // epilogue: tanh(z + bias)*u, reduce over this warp's 64 cols, atomic to g_ait
    float s[4] = {0.f, 0.f, 0.f, 0.f};   // [mt*2 + hi]
    #pragma unroll
    for (int nt = 0; nt < 8; nt++){
        int col = col0 + warp_n + nt*8 + (lane & 3)*2;
        float b0v = bias[col], b1v = bias[col+1];
        float u0v = u[col],    u1v = u[col+1];
        #pragma unroll
        for (int mt = 0; mt < 2; mt++){
            s[mt*2+0] += tanha(acc[mt][nt][0] + b0v)*u0v + tanha(acc[mt][nt][1] + b1v)*u1v;
            s[mt*2+1] += tanha(acc[mt][nt][2] + b0v)*u0v + tanha(acc[mt][nt][3] + b1v)*u1v;
        }
    }
    #pragma unroll
    for (int i = 0; i < 4; i++){
        s[i] += __shfl_xor_sync(0xffffffffu, s[i], 1);
        s[i] += __shfl_xor_sync(0xffffffffu, s[i], 2);
    }
    if ((lane & 3) == 0){
        int rbase = row0 + warp_m + (lane >> 2);
        atomicAdd(&g_ait[rbase +  0], s[0]);
        atomicAdd(&g_ait[rbase +  8], s[1]);
        atomicAdd(&g_ait[rbase + 16], s[2]);
        atomicAdd(&g_ait[rbase + 24], s[3]);
    }
}

// ---------------- Kernel 2: per-batch exp + normalize over T ----------------
__global__ __launch_bounds__(256) void softmax_norm()
{
    const int b = blockIdx.x;
    const int tid = threadIdx.x;
    __shared__ float red[256];

    float e[8];
    float ssum = 0.f;
    #pragma unroll
    for (int i = 0; i < 8; i++) {
        float v = g_ait[b * SEQT + i * 256 + tid];
        e[i] = expf(v);
        ssum += e[i];
    }
    red[tid] = ssum;
    __syncthreads();
    #pragma unroll
    for (int stride = 128; stride > 0; stride >>= 1) {
        if (tid < stride) red[tid] += red[tid + stride];
        __syncthreads();
    }
    float inv = 1.0f / (red[0] + 1e-7f);
    #pragma unroll
    for (int i = 0; i < 8; i++)
        g_a[b * SEQT + i * 256 + tid] = e[i] * inv;
}

// ---------------- Kernel 3: weighted pooling out[b,d] = sum_t x*a -----------
__global__ __launch_bounds__(256) void pool(
    const float* __restrict__ x, float* __restrict__ out)
{
    const int b  = blockIdx.x;
    const int tc = blockIdx.y;
    const int tid = threadIdx.x;
    __shared__ float sa[128];

    if (tid < 128)
        sa[tid] = g_a[b * SEQT + tc * 128 + tid];
    __syncthreads();

    const float* xp = x + (size_t)b * SEQT * DIM + (size_t)tc * 128 * DIM;
    float acc0 = 0.f, acc1 = 0.f;
    #pragma unroll 4
    for (int t = 0; t < 128; t++) {
        float av = sa[t];
        acc0 = fmaf(xp[(size_t)t * DIM + tid],       av, acc0);
        acc1 = fmaf(xp[(size_t)t * DIM + tid + 256], av, acc1);
    }
    atomicAdd(&out[b * DIM + tid],       acc0);
    atomicAdd(&out[b * DIM + tid + 256], acc1);
}

// ---------------------------------------------------------------------------
extern "C" void kernel_launch(void* const* d_in, const int* in_sizes, int n_in,
                              void* d_out, int out_size)
{
    const float* x    = (const float*)d_in[0];
    const float* W    = (const float*)d_in[1];
    const float* bias = (const float*)d_in[2];
    const float* u    = (const float*)d_in[3];
    float* out = (float*)d_out;

    void* aitp = nullptr;
    cudaGetSymbolAddress(&aitp, g_ait);
    cudaMemsetAsync(aitp, 0, ROWS * sizeof(float));
    cudaMemsetAsync(d_out, 0, BATCH * DIM * sizeof(float));

    prep_x<<<(ROWS*DIM)/(256*8), 256>>>(x);
    prep_w<<<DIM, 256>>>(W);
    gemm_tc<<<dim3(DIM/BN, ROWS/BM), 256>>>(bias, u);
    softmax_norm<<<BATCH, 256>>>();
    pool<<<dim3(BATCH, 16), 256>>>(x, out);
}